// round 4
// baseline (speedup 1.0000x reference)
#include <cuda_runtime.h>
#include <cstdint>
#include <cstddef>

// Problem constants
#define BB   256     // batch
#define SS   512     // seq len
#define VV   50000   // vocab
#define EE   300     // embed dim
#define HH   128     // hidden
#define NG   1024    // 2 dirs * 4H gate columns

// ---------------------------------------------------------------------------
// Scratch (static device globals — no runtime allocation allowed)
// ---------------------------------------------------------------------------
__device__ __align__(16) float g_P  [(size_t)VV * NG];        // projected vocab table (+b0 folded)
__device__ __align__(16) float g_h0 [(size_t)SS * BB * 256];  // layer-0 output [s*B+b][2H]
__device__ __align__(16) float g_gx1[(size_t)SS * BB * NG];   // layer-1 input projections (+b1 folded)
__device__ __align__(16) float g_hT [(size_t)BB * 256];       // layer-1 final hidden [b][2H]

// ---------------------------------------------------------------------------
// Packed fp32x2 helpers — clean u64 dataflow (no aliasing UB; asm outputs are
// genuinely consumed so the non-volatile asm cannot be dead-coded).
// ---------------------------------------------------------------------------
__device__ __forceinline__ void ffma2(unsigned long long& c,
                                      unsigned long long a,
                                      unsigned long long b) {
    asm("fma.rn.f32x2 %0, %1, %2, %0;" : "+l"(c) : "l"(a), "l"(b));
}
__device__ __forceinline__ unsigned long long bcast2(float x) {
    unsigned long long r;
    asm("mov.b64 %0, {%1, %1};" : "=l"(r) : "f"(x));
    return r;
}
__device__ __forceinline__ float2 unpk2(unsigned long long v) {
    float2 f;
    asm("mov.b64 {%0, %1}, %2;" : "=f"(f.x), "=f"(f.y) : "l"(v));
    return f;
}

__device__ __forceinline__ float sigm_f(float x) {
    return 1.0f / (1.0f + __expf(-x));
}
__device__ __forceinline__ float tanh_f(float x) {
    float a = fabsf(x);
    float t = __expf(-2.0f * a);
    float r = (1.0f - t) / (1.0f + t);
    return copysignf(r, x);
}

// ---------------------------------------------------------------------------
// GEMM: C[M,1024] = A[M,K] @ Bw[1024,K]^T + bias[1024]
// BM=128, BN=128, BK=16, 256 threads, 8x8 per-thread microtile, f32x2 packed
// along M pairs. WHICH==0: A=Aarg, C=g_P.  WHICH==1: A=g_h0, C=g_gx1.
// ---------------------------------------------------------------------------
template<int WHICH>
__global__ __launch_bounds__(256, 2)
void gemm_bias_kernel(const float* __restrict__ Aarg,
                      const float* __restrict__ Bw,
                      const float* __restrict__ bias,
                      int M, int K)
{
    const float* __restrict__ A = (WHICH == 0) ? Aarg : g_h0;
    float* __restrict__ C       = (WHICH == 0) ? g_P  : g_gx1;

    __shared__ __align__(16) float As[16][128];
    __shared__ __align__(16) float Bs[16][128];

    const int tid   = threadIdx.x;
    const int mTile = blockIdx.y * 128;
    const int nTile = blockIdx.x * 128;
    const int n_base = (tid & 15) * 8;
    const int m_base = (tid >> 4) * 8;

    unsigned long long acc[4][8];
    #pragma unroll
    for (int i = 0; i < 4; i++)
        #pragma unroll
        for (int j = 0; j < 8; j++) acc[i][j] = 0ull;

    const int lr = tid >> 2;          // 0..63
    const int lk = (tid & 3) * 4;     // 0,4,8,12

    const int nKT = (K + 15) >> 4;
    for (int kt = 0; kt < nKT; kt++) {
        const int k0 = kt << 4;
        // ---- load A tile (transposed into smem); K % 4 == 0 for both cases
        #pragma unroll
        for (int i = 0; i < 2; i++) {
            int row = lr + i * 64;
            int gm  = mTile + row;
            int gk  = k0 + lk;
            float4 v = make_float4(0.f, 0.f, 0.f, 0.f);
            if (gm < M && gk < K)
                v = *reinterpret_cast<const float4*>(&A[(size_t)gm * K + gk]);
            As[lk + 0][row] = v.x; As[lk + 1][row] = v.y;
            As[lk + 2][row] = v.z; As[lk + 3][row] = v.w;
        }
        // ---- load B tile (N rows always valid: N==1024)
        #pragma unroll
        for (int i = 0; i < 2; i++) {
            int row = lr + i * 64;
            int gn  = nTile + row;
            int gk  = k0 + lk;
            float4 v = make_float4(0.f, 0.f, 0.f, 0.f);
            if (gk < K)
                v = *reinterpret_cast<const float4*>(&Bw[(size_t)gn * K + gk]);
            Bs[lk + 0][row] = v.x; Bs[lk + 1][row] = v.y;
            Bs[lk + 2][row] = v.z; Bs[lk + 3][row] = v.w;
        }
        __syncthreads();

        #pragma unroll
        for (int k = 0; k < 16; k++) {
            ulonglong2 a01 = *reinterpret_cast<const ulonglong2*>(&As[k][m_base]);
            ulonglong2 a23 = *reinterpret_cast<const ulonglong2*>(&As[k][m_base + 4]);
            float4 b0 = *reinterpret_cast<const float4*>(&Bs[k][n_base]);
            float4 b1 = *reinterpret_cast<const float4*>(&Bs[k][n_base + 4]);
            unsigned long long bbk[8] = {
                bcast2(b0.x), bcast2(b0.y), bcast2(b0.z), bcast2(b0.w),
                bcast2(b1.x), bcast2(b1.y), bcast2(b1.z), bcast2(b1.w)
            };
            #pragma unroll
            for (int j = 0; j < 8; j++) {
                ffma2(acc[0][j], a01.x, bbk[j]);
                ffma2(acc[1][j], a01.y, bbk[j]);
                ffma2(acc[2][j], a23.x, bbk[j]);
                ffma2(acc[3][j], a23.y, bbk[j]);
            }
        }
        __syncthreads();
    }

    // ---- epilogue: unpack, add bias, vectorized stores
    const int gn = nTile + n_base;
    float bv[8];
    #pragma unroll
    for (int j = 0; j < 8; j++) bv[j] = bias[gn + j];

    #pragma unroll
    for (int i = 0; i < 4; i++) {
        int gm0 = mTile + m_base + 2 * i;
        float2 u[8];
        #pragma unroll
        for (int j = 0; j < 8; j++) u[j] = unpk2(acc[i][j]);
        float4 lo0 = make_float4(u[0].x + bv[0], u[1].x + bv[1], u[2].x + bv[2], u[3].x + bv[3]);
        float4 lo1 = make_float4(u[4].x + bv[4], u[5].x + bv[5], u[6].x + bv[6], u[7].x + bv[7]);
        float4 hi0 = make_float4(u[0].y + bv[0], u[1].y + bv[1], u[2].y + bv[2], u[3].y + bv[3]);
        float4 hi1 = make_float4(u[4].y + bv[4], u[5].y + bv[5], u[6].y + bv[6], u[7].y + bv[7]);
        if (gm0 < M) {
            *reinterpret_cast<float4*>(&C[(size_t)gm0 * NG + gn])     = lo0;
            *reinterpret_cast<float4*>(&C[(size_t)gm0 * NG + gn + 4]) = lo1;
        }
        if (gm0 + 1 < M) {
            *reinterpret_cast<float4*>(&C[(size_t)(gm0 + 1) * NG + gn])     = hi0;
            *reinterpret_cast<float4*>(&C[(size_t)(gm0 + 1) * NG + gn + 4]) = hi1;
        }
    }
}

// ---------------------------------------------------------------------------
// Recurrence kernel. One block = 4 batch rows x one direction x one layer.
// 512 threads. Thread t owns FULL gate row g=t (all 512 rows covered — this
// fixes the round-2 half-coverage bug): z[g,b] = gx[g,b] + w_hh[g,:] . h[b,:].
// w row split: k in [0,64) lives in registers as 32 k-pair-packed u64;
// k in [64,128) lives in smem (pitch 68 floats -> conflict-free LDS.128).
// Accumulation is f32x2 over k-pairs (lane0=even-k, lane1=odd-k partials),
// one cross-lane add at the end. h broadcast-read from smem as ulonglong2.
// Every thread is also a combiner for cell (bb=t>>7, jj=t&127), keeping c in
// a register.
// LAYER==0: gx gathered from g_P via tokens; writes h seq to g_h0 each step.
// LAYER==1: gx = g_gx1; writes final hidden to g_hT after the loop.
// Dynamic smem layout (bytes):
//   [0, 139264)            w_sm  512 rows x 68-float pitch (k 64..127 in cols 0..63)
//   [139264, 141312)       h_sm  [4][128] floats
//   [141312, 151552)       z_sm  [512][5] floats (pitch 5 -> conflict-free)
//   [151552, 159744)       tok_sm [4][512] int
// ---------------------------------------------------------------------------
#define REC_SMEM_BYTES 159744

template<int LAYER>
__global__ __launch_bounds__(512, 1)
void recur_kernel(const int* __restrict__ tokens,
                  const float* __restrict__ w_hh)   // [2,512,128]
{
    extern __shared__ __align__(16) float smem[];
    float* w_sm   = smem;                   // 512*68 floats
    float* h_sm   = smem + 512 * 68;        // 512 floats
    float* z_sm   = h_sm + 512;             // 2560 floats
    int*   tok_sm = (int*)(z_sm + 2560);    // 2048 ints

    const int tid   = threadIdx.x;
    const int chunk = blockIdx.x;   // 64 chunks of 4 batch rows
    const int dir   = blockIdx.y;   // 0 fwd, 1 bwd
    const int g     = tid;          // gate row 0..511

    // ---- w_hh row g, k 0..63 into registers as 32 packed k-pairs
    unsigned long long wr2[32];
    {
        const unsigned long long* wp = reinterpret_cast<const unsigned long long*>(
            &w_hh[((size_t)dir * 512 + g) * 128]);
        #pragma unroll
        for (int i = 0; i < 32; i++) wr2[i] = wp[i];
    }
    // ---- w_hh k 64..127 into smem (coalesced 64-float runs per row)
    for (int idx = tid; idx < 512 * 64; idx += 512) {
        int gg = idx >> 6, kk = idx & 63;
        w_sm[gg * 68 + kk] = w_hh[((size_t)dir * 512 + gg) * 128 + 64 + kk];
    }
    if (LAYER == 0) {
        for (int idx = tid; idx < 4 * 512; idx += 512)
            tok_sm[idx] = tokens[(size_t)(chunk * 4 + (idx >> 9)) * SS + (idx & 511)];
    }
    h_sm[tid] = 0.0f;   // 512 entries, one per thread
    __syncthreads();

    const int jj = tid & 127;   // hidden unit of this combiner thread
    const int bb = tid >> 7;    // batch row (0..3) of this combiner thread
    const int col = dir * 512 + g;
    const float* __restrict__ gsrc = (LAYER == 0) ? g_P : g_gx1;
    float c_st = 0.0f, h_last = 0.0f;

    for (int si = 0; si < 512; si++) {
        const int s = dir ? (511 - si) : si;

        // --- input projections (issued early; latency hidden behind FMAs)
        float gxv[4];
        #pragma unroll
        for (int b = 0; b < 4; b++) {
            size_t row = (LAYER == 0)
                ? (size_t)tok_sm[b * 512 + s]
                : ((size_t)s * BB + (chunk * 4 + b));
            gxv[b] = gsrc[row * NG + col];
        }

        // --- full-k dot for this gate row, 4 batch cols, f32x2 over k-pairs
        unsigned long long acc[4] = {0ull, 0ull, 0ull, 0ull};
        #pragma unroll
        for (int t = 0; t < 16; t++) {          // register half: k = 4t..4t+3
            #pragma unroll
            for (int b = 0; b < 4; b++) {
                ulonglong2 h2 = *reinterpret_cast<const ulonglong2*>(&h_sm[b * 128 + t * 4]);
                ffma2(acc[b], wr2[2 * t],     h2.x);
                ffma2(acc[b], wr2[2 * t + 1], h2.y);
            }
        }
        const float* wrow = &w_sm[g * 68];
        #pragma unroll
        for (int t = 0; t < 16; t++) {          // smem half: k = 64 + 4t..
            ulonglong2 w2 = *reinterpret_cast<const ulonglong2*>(&wrow[t * 4]);
            #pragma unroll
            for (int b = 0; b < 4; b++) {
                ulonglong2 h2 = *reinterpret_cast<const ulonglong2*>(&h_sm[b * 128 + 64 + t * 4]);
                ffma2(acc[b], w2.x, h2.x);
                ffma2(acc[b], w2.y, h2.y);
            }
        }
        #pragma unroll
        for (int b = 0; b < 4; b++) {
            float2 f = unpk2(acc[b]);
            z_sm[g * 5 + b] = f.x + f.y + gxv[b];
        }
        __syncthreads();

        // --- gate combine (torch order i,f,g,o) for cell (bb, jj)
        {
            float zi = z_sm[(      jj) * 5 + bb];
            float zf = z_sm[(128 + jj) * 5 + bb];
            float zg = z_sm[(256 + jj) * 5 + bb];
            float zo = z_sm[(384 + jj) * 5 + bb];
            float ig = sigm_f(zi), fg = sigm_f(zf), og = sigm_f(zo);
            float gv = tanh_f(zg);
            c_st = fg * c_st + ig * gv;
            float hh = og * tanh_f(c_st);
            h_last = hh;
            h_sm[bb * 128 + jj] = hh;
            if (LAYER == 0)
                g_h0[((size_t)s * BB + (chunk * 4 + bb)) * 256 + dir * 128 + jj] = hh;
        }
        __syncthreads();
    }

    if (LAYER == 1)
        g_hT[(size_t)(chunk * 4 + bb) * 256 + dir * 128 + jj] = h_last;
}

// ---------------------------------------------------------------------------
// FC head: out[b] = relu(hT[b] @ fc1_w^T + fc1_b) @ fc2_w^T + fc2_b
// One block (128 threads) per batch row. Negligible runtime.
// ---------------------------------------------------------------------------
__global__ __launch_bounds__(128)
void fc_kernel(const float* __restrict__ fc1w, const float* __restrict__ fc1b,
               const float* __restrict__ fc2w, const float* __restrict__ fc2b,
               float* __restrict__ out)
{
    __shared__ float xs[256];
    __shared__ float red[4];
    const int b = blockIdx.x, tid = threadIdx.x;
    xs[tid]       = g_hT[(size_t)b * 256 + tid];
    xs[tid + 128] = g_hT[(size_t)b * 256 + 128 + tid];
    __syncthreads();

    float s = fc1b[tid];
    const float* wr = &fc1w[(size_t)tid * 256];
    #pragma unroll 8
    for (int k = 0; k < 256; k++) s += xs[k] * wr[k];
    float a = fmaxf(s, 0.0f);

    for (int o = 0; o < 2; o++) {
        float v = a * fc2w[o * 128 + tid];
        #pragma unroll
        for (int off = 16; off > 0; off >>= 1)
            v += __shfl_xor_sync(0xffffffffu, v, off);
        if ((tid & 31) == 0) red[tid >> 5] = v;
        __syncthreads();
        if (tid == 0)
            out[b * 2 + o] = red[0] + red[1] + red[2] + red[3] + fc2b[o];
        __syncthreads();
    }
}

// ---------------------------------------------------------------------------
// Launcher (graph-capturable: kernel launches only, default stream)
// ---------------------------------------------------------------------------
extern "C" void kernel_launch(void* const* d_in, const int* in_sizes, int n_in,
                              void* d_out, int out_size)
{
    const int*   tokens = (const int*)  d_in[0];   // [B,S]
    const float* emb    = (const float*)d_in[1];   // [V,E]
    const float* w_ih0  = (const float*)d_in[2];   // [2,4H,E]  -> flat [1024,300]
    const float* w_hh0  = (const float*)d_in[3];   // [2,4H,H]
    const float* b0     = (const float*)d_in[4];   // [2,4H]    -> flat [1024]
    const float* w_ih1  = (const float*)d_in[5];   // [2,4H,2H] -> flat [1024,256]
    const float* w_hh1  = (const float*)d_in[6];   // [2,4H,H]
    const float* b1     = (const float*)d_in[7];   // [2,4H]
    const float* fc1w   = (const float*)d_in[8];   // [H,2H]
    const float* fc1b   = (const float*)d_in[9];   // [H]
    const float* fc2w   = (const float*)d_in[10];  // [2,H]
    const float* fc2b   = (const float*)d_in[11];  // [2]
    float* out = (float*)d_out;

    static int configured = 0;
    if (!configured) {
        cudaFuncSetAttribute((const void*)recur_kernel<0>,
                             cudaFuncAttributeMaxDynamicSharedMemorySize, REC_SMEM_BYTES);
        cudaFuncSetAttribute((const void*)recur_kernel<1>,
                             cudaFuncAttributeMaxDynamicSharedMemorySize, REC_SMEM_BYTES);
        configured = 1;
    }

    // 1) Projected vocab table: P = emb @ w_ih0^T + b0   [50000,1024]
    {
        dim3 grid(NG / 128, (VV + 127) / 128);   // (8, 391)
        gemm_bias_kernel<0><<<grid, 256>>>(emb, w_ih0, b0, VV, EE);
    }
    // 2) Layer-0 bidirectional recurrence (gx gathered from P)
    {
        dim3 grid(64, 2);
        recur_kernel<0><<<grid, 512, REC_SMEM_BYTES>>>(tokens, w_hh0);
    }
    // 3) Layer-1 input projections: gx1 = h0_seq @ w_ih1^T + b1  [131072,1024]
    {
        dim3 grid(NG / 128, (SS * BB) / 128);    // (8, 1024)
        gemm_bias_kernel<1><<<grid, 256>>>(nullptr, w_ih1, b1, SS * BB, 256);
    }
    // 4) Layer-1 bidirectional recurrence -> final hidden states
    {
        dim3 grid(64, 2);
        recur_kernel<1><<<grid, 512, REC_SMEM_BYTES>>>(tokens, w_hh1);
    }
    // 5) MLP head
    fc_kernel<<<BB, 128>>>(fc1w, fc1b, fc2w, fc2b, out);
}